// round 2
// baseline (speedup 1.0000x reference)
#include <cuda_runtime.h>
#include <math.h>

#define B_ 64
#define T_ 30
#define S_ 31
#define E_ 128
#define U_ 256
#define V_ 32000

// ---------------- device scratch (no allocations allowed) ----------------
__device__ float g_keys[B_ * S_ * U_];        // [b][s][v]  (b*31+s)*256
__device__ float g_xemb[B_ * T_ * E_];        // row m = t*64+b
__device__ float g_xw[B_ * T_ * 4 * U_];      // row m = t*64+b : x@Wk[:E] + b_lstm
__device__ float g_Wrc[2 * U_ * 4 * U_];      // [512][1024] combined recurrent weight
__device__ float g_hbuf[2][B_ * U_];          // ping-pong h
__device__ float g_c[B_ * U_];
__device__ float g_ctx[B_ * U_];
__device__ float g_hc[B_ * T_ * 2 * U_];      // row m = b*30+t : [h(256), ctx(256)]
__device__ float g_attn[B_ * T_ * U_];        // row m = b*30+t

__device__ __forceinline__ float sigm(float x) { return 1.0f / (1.0f + expf(-x)); }

// ---------------- init: h, c, ctx ----------------
__global__ void k_init(const float* __restrict__ h0, const float* __restrict__ c0) {
    int i = blockIdx.x * blockDim.x + threadIdx.x;
    if (i < B_ * U_) {
        g_hbuf[0][i] = h0[i];
        g_c[i] = c0[i];
        g_ctx[i] = 0.0f;
    }
}

// ---------------- gather embeddings (int32/int64 autodetect) ----------------
__global__ void k_gather(const void* __restrict__ in_raw, const float* __restrict__ emb) {
    const int m = blockIdx.x;            // m = t*64 + b
    const int t = m >> 6;
    const int b = m & 63;
    const int* p32 = (const int*)in_raw;
    bool is64 = true;
#pragma unroll
    for (int i = 1; i <= 15; i += 2)
        if (p32[i] != 0) is64 = false;
    const int pos = b * T_ + t;
    long long idx = is64 ? ((const long long*)in_raw)[pos] : (long long)p32[pos];
    g_xemb[m * E_ + threadIdx.x] = emb[idx * E_ + threadIdx.x];
}

// ---------------- generic tiled SGEMM: C = A@B (+bias), row-major ----------------
// requires M%BM==0, N%BN==0, K%BK==0 (guaranteed by call sites)
template <int BM, int BN, int BK, int TM, int TN>
__global__ __launch_bounds__(256) void sgemm_kernel(
    const float* __restrict__ A, const float* __restrict__ B,
    const float* __restrict__ bias, float* __restrict__ C,
    int M, int N, int K)
{
    constexpr int TX = BN / TN;   // 16
    __shared__ float As[BK][BM];
    __shared__ float Bs[BK][BN];
    const int tid = threadIdx.x;
    const int tx = tid % TX;
    const int ty = tid / TX;
    const int row0 = blockIdx.y * BM;
    const int col0 = blockIdx.x * BN;

    const int a_m = tid / (BK / 4);
    const int a_k = (tid % (BK / 4)) * 4;
    const int b_k = tid / (BN / 4);
    const int b_n = (tid % (BN / 4)) * 4;

    float acc[TM][TN];
#pragma unroll
    for (int i = 0; i < TM; i++)
#pragma unroll
        for (int j = 0; j < TN; j++) acc[i][j] = 0.0f;

    for (int k0 = 0; k0 < K; k0 += BK) {
        float4 av = *reinterpret_cast<const float4*>(&A[(size_t)(row0 + a_m) * K + k0 + a_k]);
        As[a_k + 0][a_m] = av.x;
        As[a_k + 1][a_m] = av.y;
        As[a_k + 2][a_m] = av.z;
        As[a_k + 3][a_m] = av.w;
        *reinterpret_cast<float4*>(&Bs[b_k][b_n]) =
            *reinterpret_cast<const float4*>(&B[(size_t)(k0 + b_k) * N + col0 + b_n]);
        __syncthreads();
#pragma unroll
        for (int k = 0; k < BK; k++) {
            float ra[TM], rb[TN];
#pragma unroll
            for (int i = 0; i < TM; i++) ra[i] = As[k][ty * TM + i];
#pragma unroll
            for (int j = 0; j < TN; j++) rb[j] = Bs[k][tx * TN + j];
#pragma unroll
            for (int i = 0; i < TM; i++)
#pragma unroll
                for (int j = 0; j < TN; j++) acc[i][j] += ra[i] * rb[j];
        }
        __syncthreads();
    }

    float bj[TN];
#pragma unroll
    for (int j = 0; j < TN; j++)
        bj[j] = bias ? bias[col0 + tx * TN + j] : 0.0f;

#pragma unroll
    for (int i = 0; i < TM; i++) {
        const size_t row = row0 + ty * TM + i;
#pragma unroll
        for (int j = 0; j < TN; j += 4) {
            float4 v;
            v.x = acc[i][j + 0] + bj[j + 0];
            v.y = acc[i][j + 1] + bj[j + 1];
            v.z = acc[i][j + 2] + bj[j + 2];
            v.w = acc[i][j + 3] + bj[j + 3];
            *reinterpret_cast<float4*>(&C[row * N + col0 + tx * TN + j]) = v;
        }
    }
}

// ---------------- W_rc[0:256] += W_r ----------------
__global__ void k_addWr(const float* __restrict__ Wr) {
    int i = blockIdx.x * blockDim.x + threadIdx.x;
    if (i < U_ * 4 * U_) g_Wrc[i] += Wr[i];
}

// ---------------- per-step: z GEMM + LSTM ----------------
// grid 128 blocks (2 u's each), 256 threads. Kz==256 -> t==0 path (Wz=W_r, A=h only)
__global__ __launch_bounds__(256) void step_a_kernel(
    int t, const float* __restrict__ Wr_in, int Kz)
{
    const int u0 = blockIdx.x * 2;
    const int tid = threadIdx.x;
    const int b = tid & 63;
    const int q = tid >> 6;   // gate 0..3
    const int ping = t & 1;
    const float* __restrict__ hprev = g_hbuf[ping];
    float* __restrict__ hnew = g_hbuf[1 - ping];
    const float* __restrict__ Wz = (Kz == 256) ? Wr_in : g_Wrc;

    __shared__ float As[32][65];     // padded: conflict-free transpose stores
    __shared__ float2 Ws[32][4];
    __shared__ float zs[64][8];

    const float* xwt = g_xw + (size_t)(t * 64 + b) * 1024;
    const int j0 = q * 256 + u0;
    float acc0 = xwt[j0];
    float acc1 = xwt[j0 + 1];

    for (int k0 = 0; k0 < Kz; k0 += 32) {
        // A tile: 64 rows x 32 k  (512 float4, 2 per thread), coalesced
#pragma unroll
        for (int r = 0; r < 2; r++) {
            int idx = tid + r * 256;          // 0..511
            int ab = idx >> 3;                // batch 0..63
            int kf = (idx & 7) * 4;           // 0..28
            int kg = k0 + kf;
            const float* src = (kg < 256) ? (hprev + ab * 256 + kg)
                                          : (g_ctx + ab * 256 + (kg - 256));
            float4 v = *reinterpret_cast<const float4*>(src);
            As[kf + 0][ab] = v.x;
            As[kf + 1][ab] = v.y;
            As[kf + 2][ab] = v.z;
            As[kf + 3][ab] = v.w;
        }
        // W tile: 32 k x 8 cols (col c=2g+e -> j = g*256 + u0 + e)
        {
            int k = tid >> 3;
            int c = tid & 7;
            int j = (c >> 1) * 256 + u0 + (c & 1);
            ((float*)Ws)[k * 8 + c] = Wz[(size_t)(k0 + k) * 1024 + j];
        }
        __syncthreads();
#pragma unroll
        for (int k = 0; k < 32; k++) {
            float a = As[k][b];
            float2 w = Ws[k][q];
            acc0 += a * w.x;
            acc1 += a * w.y;
        }
        __syncthreads();
    }

    zs[b][q * 2 + 0] = acc0;
    zs[b][q * 2 + 1] = acc1;
    __syncthreads();

    if (tid < 128) {
        int du = tid >> 6;
        int bb = tid & 63;
        int u = u0 + du;
        float zi = zs[bb][0 + du];
        float zf = zs[bb][2 + du];
        float zg = zs[bb][4 + du];
        float zo = zs[bb][6 + du];
        float cold = g_c[bb * 256 + u];
        float cn = sigm(zf) * cold + sigm(zi) * tanhf(zg);
        g_c[bb * 256 + u] = cn;
        float h = sigm(zo) * tanhf(cn);
        hnew[bb * 256 + u] = h;
        g_hc[(size_t)(bb * T_ + t) * 512 + u] = h;
    }
}

// ---------------- per-step: attention (scores, softmax, context) ----------------
// grid 64 (one per batch), 256 threads
__global__ __launch_bounds__(256) void step_b_kernel(int t, const float* __restrict__ mem)
{
    const int b = blockIdx.x;
    const int tid = threadIdx.x;
    const int w = tid >> 5;
    const int l = tid & 31;
    const float* __restrict__ hcur = g_hbuf[1 - (t & 1)];

    __shared__ float hs[256];
    __shared__ float sc[32];
    __shared__ float al[32];

    hs[tid] = hcur[b * 256 + tid];
    __syncthreads();

    for (int s = w; s < S_; s += 8) {
        const float* kp = g_keys + (size_t)(b * S_ + s) * 256;
        float d = 0.0f;
#pragma unroll
        for (int i = 0; i < 8; i++) d += hs[l + 32 * i] * kp[l + 32 * i];
#pragma unroll
        for (int o = 16; o > 0; o >>= 1) d += __shfl_down_sync(0xffffffffu, d, o);
        if (l == 0) sc[s] = d;
    }
    __syncthreads();

    if (w == 0) {
        float v = (l < S_) ? sc[l] : -INFINITY;
        float mx = v;
#pragma unroll
        for (int o = 16; o > 0; o >>= 1) mx = fmaxf(mx, __shfl_xor_sync(0xffffffffu, mx, o));
        float e = (l < S_) ? expf(v - mx) : 0.0f;
        float sm = e;
#pragma unroll
        for (int o = 16; o > 0; o >>= 1) sm += __shfl_xor_sync(0xffffffffu, sm, o);
        if (l < S_) al[l] = e / sm;
    }
    __syncthreads();

    // context[u]
    float c = 0.0f;
    const int u = tid;
#pragma unroll 1
    for (int s = 0; s < S_; s++)
        c += al[s] * mem[(size_t)(b * S_ + s) * 256 + u];
    g_ctx[b * 256 + u] = c;
    g_hc[(size_t)(b * T_ + t) * 512 + 256 + u] = c;
}

// ---------------- launcher ----------------
extern "C" void kernel_launch(void* const* d_in, const int* in_sizes, int n_in,
                              void* d_out, int out_size)
{
    const void*  inputs   = d_in[0];
    const float* memory   = (const float*)d_in[1];
    const float* sample_h = (const float*)d_in[2];
    const float* sample_c = (const float*)d_in[3];
    const float* emb      = (const float*)d_in[4];
    const float* W_k      = (const float*)d_in[5];   // [384][1024]
    const float* W_r      = (const float*)d_in[6];   // [256][1024]
    const float* b_lstm   = (const float*)d_in[7];   // [1024]
    const float* W_mem    = (const float*)d_in[8];   // [256][256]
    const float* W_attn   = (const float*)d_in[9];   // [512][256]
    const float* W_fc     = (const float*)d_in[10];  // [256][32000]
    const float* b_fc     = (const float*)d_in[11];  // [32000]
    float* out = (float*)d_out;

    float *p_keys, *p_xemb, *p_xw, *p_Wrc, *p_hc, *p_attn;
    cudaGetSymbolAddress((void**)&p_keys, g_keys);
    cudaGetSymbolAddress((void**)&p_xemb, g_xemb);
    cudaGetSymbolAddress((void**)&p_xw, g_xw);
    cudaGetSymbolAddress((void**)&p_Wrc, g_Wrc);
    cudaGetSymbolAddress((void**)&p_hc, g_hc);
    cudaGetSymbolAddress((void**)&p_attn, g_attn);

    // init state
    k_init<<<64, 256>>>(sample_h, sample_c);
    // gather embeddings
    k_gather<<<B_ * T_, E_>>>(inputs, emb);
    // keys = memory @ W_mem          [1984,256] = [1984,256]@[256,256]
    sgemm_kernel<64, 64, 16, 4, 4><<<dim3(4, 31), 256>>>(memory, W_mem, nullptr, p_keys, 1984, 256, 256);
    // xw = xemb @ W_k[:128] + b_lstm [1920,1024] = [1920,128]@[128,1024]
    sgemm_kernel<64, 64, 16, 4, 4><<<dim3(16, 30), 256>>>(p_xemb, W_k, b_lstm, p_xw, 1920, 1024, 128);
    // W_comb = W_attn @ W_k[128:]    [512,1024] = [512,256]@[256,1024]
    sgemm_kernel<64, 64, 16, 4, 4><<<dim3(16, 8), 256>>>(W_attn, W_k + 128 * 1024, nullptr, p_Wrc, 512, 1024, 256);
    // W_rc[:256] += W_r
    k_addWr<<<256, 1024>>>(W_r);

    // recurrence
    for (int t = 0; t < T_; t++) {
        if (t == 0)
            step_a_kernel<<<128, 256>>>(t, W_r, 256);
        else
            step_a_kernel<<<128, 256>>>(t, W_r, 512);
        step_b_kernel<<<64, 256>>>(t, memory);
    }

    // attn_seq = hc_seq @ W_attn     [1920,256] = [1920,512]@[512,256]
    sgemm_kernel<64, 64, 16, 4, 4><<<dim3(4, 30), 256>>>(p_hc, W_attn, nullptr, p_attn, 1920, 256, 512);
    // out = attn_seq @ W_fc + b_fc   [1920,32000] = [1920,256]@[256,32000]
    sgemm_kernel<128, 128, 8, 8, 8><<<dim3(250, 15), 256>>>(p_attn, W_fc, b_fc, out, 1920, 32000, 256);
}

// round 5
// speedup vs baseline: 1.2524x; 1.2524x over previous
#include <cuda_runtime.h>
#include <cuda_bf16.h>
#include <math.h>
#include <stdint.h>

#define B_ 64
#define T_ 30
#define S_ 31
#define E_ 128
#define U_ 256
#define V_ 32000

#define FC_K   768
#define FC_NS  24          // K stages of 32

// ---------------- device scratch (no allocations allowed) ----------------
__device__ float g_keys[B_ * S_ * U_];
__device__ float g_xemb[B_ * T_ * E_];
__device__ float g_xw[B_ * T_ * 4 * U_];
__device__ float g_Wrc[2 * U_ * 4 * U_];
__device__ float g_hbuf[2][B_ * U_];
__device__ float g_c[B_ * U_];
__device__ float g_ctx[B_ * U_];
__device__ float g_hc[B_ * T_ * 2 * U_];
__device__ float g_attn[B_ * T_ * U_];
__device__ __nv_bfloat16 g_Abf[B_ * T_ * FC_K];       // [1920][768]  hi|lo|hi
__device__ __nv_bfloat16 g_Wt[(size_t)V_ * FC_K];     // [32000][768] hi|hi|lo

__device__ __forceinline__ float sigm(float x) { return 1.0f / (1.0f + expf(-x)); }
__device__ __forceinline__ uint32_t smem_u32(const void* p) {
    return (uint32_t)__cvta_generic_to_shared(p);
}
__device__ __forceinline__ void cp16(uint32_t dst, const void* src) {
    asm volatile("cp.async.cg.shared.global [%0], [%1], 16;" :: "r"(dst), "l"(src));
}
__device__ __forceinline__ void ldm_x4(uint32_t* r, uint32_t addr) {
    asm volatile("ldmatrix.sync.aligned.m8n8.x4.shared.b16 {%0,%1,%2,%3}, [%4];"
                 : "=r"(r[0]), "=r"(r[1]), "=r"(r[2]), "=r"(r[3]) : "r"(addr));
}
__device__ __forceinline__ void mma16816(float* c, const uint32_t* a, uint32_t b0, uint32_t b1) {
    asm volatile(
        "mma.sync.aligned.m16n8k16.row.col.f32.bf16.bf16.f32 "
        "{%0,%1,%2,%3}, {%4,%5,%6,%7}, {%8,%9}, {%0,%1,%2,%3};"
        : "+f"(c[0]), "+f"(c[1]), "+f"(c[2]), "+f"(c[3])
        : "r"(a[0]), "r"(a[1]), "r"(a[2]), "r"(a[3]), "r"(b0), "r"(b1));
}

// ---------------- init ----------------
__global__ void k_init(const float* __restrict__ h0, const float* __restrict__ c0) {
    int i = blockIdx.x * blockDim.x + threadIdx.x;
    if (i < B_ * U_) {
        g_hbuf[0][i] = h0[i];
        g_c[i] = c0[i];
        g_ctx[i] = 0.0f;
    }
}

// ---------------- gather embeddings (int32/int64 autodetect) ----------------
__global__ void k_gather(const void* __restrict__ in_raw, const float* __restrict__ emb) {
    const int m = blockIdx.x;
    const int t = m >> 6;
    const int b = m & 63;
    const int* p32 = (const int*)in_raw;
    bool is64 = true;
#pragma unroll
    for (int i = 1; i <= 15; i += 2)
        if (p32[i] != 0) is64 = false;
    const int pos = b * T_ + t;
    long long idx = is64 ? ((const long long*)in_raw)[pos] : (long long)p32[pos];
    g_xemb[m * E_ + threadIdx.x] = emb[idx * E_ + threadIdx.x];
}

// ---------------- generic fp32 tiled SGEMM (small GEMMs only) ----------------
template <int BM, int BN, int BK, int TM, int TN>
__global__ __launch_bounds__(256) void sgemm_kernel(
    const float* __restrict__ A, const float* __restrict__ B,
    const float* __restrict__ bias, float* __restrict__ C,
    int M, int N, int K)
{
    constexpr int TX = BN / TN;
    __shared__ float As[BK][BM];
    __shared__ float Bs[BK][BN];
    const int tid = threadIdx.x;
    const int tx = tid % TX;
    const int ty = tid / TX;
    const int row0 = blockIdx.y * BM;
    const int col0 = blockIdx.x * BN;

    const int a_m = tid / (BK / 4);
    const int a_k = (tid % (BK / 4)) * 4;
    const int b_k = tid / (BN / 4);
    const int b_n = (tid % (BN / 4)) * 4;

    float acc[TM][TN];
#pragma unroll
    for (int i = 0; i < TM; i++)
#pragma unroll
        for (int j = 0; j < TN; j++) acc[i][j] = 0.0f;

    for (int k0 = 0; k0 < K; k0 += BK) {
        float4 av = *reinterpret_cast<const float4*>(&A[(size_t)(row0 + a_m) * K + k0 + a_k]);
        As[a_k + 0][a_m] = av.x;
        As[a_k + 1][a_m] = av.y;
        As[a_k + 2][a_m] = av.z;
        As[a_k + 3][a_m] = av.w;
        *reinterpret_cast<float4*>(&Bs[b_k][b_n]) =
            *reinterpret_cast<const float4*>(&B[(size_t)(k0 + b_k) * N + col0 + b_n]);
        __syncthreads();
#pragma unroll
        for (int k = 0; k < BK; k++) {
            float ra[TM], rb[TN];
#pragma unroll
            for (int i = 0; i < TM; i++) ra[i] = As[k][ty * TM + i];
#pragma unroll
            for (int j = 0; j < TN; j++) rb[j] = Bs[k][tx * TN + j];
#pragma unroll
            for (int i = 0; i < TM; i++)
#pragma unroll
                for (int j = 0; j < TN; j++) acc[i][j] += ra[i] * rb[j];
        }
        __syncthreads();
    }

    float bj[TN];
#pragma unroll
    for (int j = 0; j < TN; j++)
        bj[j] = bias ? bias[col0 + tx * TN + j] : 0.0f;

#pragma unroll
    for (int i = 0; i < TM; i++) {
        const size_t row = row0 + ty * TM + i;
#pragma unroll
        for (int j = 0; j < TN; j += 4) {
            float4 v;
            v.x = acc[i][j + 0] + bj[j + 0];
            v.y = acc[i][j + 1] + bj[j + 1];
            v.z = acc[i][j + 2] + bj[j + 2];
            v.w = acc[i][j + 3] + bj[j + 3];
            *reinterpret_cast<float4*>(&C[row * N + col0 + tx * TN + j]) = v;
        }
    }
}

__global__ void k_addWr(const float* __restrict__ Wr) {
    int i = blockIdx.x * blockDim.x + threadIdx.x;
    if (i < U_ * 4 * U_) g_Wrc[i] += Wr[i];
}

// ---------------- per-step: z GEMM + LSTM ----------------
__global__ __launch_bounds__(256) void step_a_kernel(
    int t, const float* __restrict__ Wr_in, int Kz)
{
    const int u0 = blockIdx.x * 2;
    const int tid = threadIdx.x;
    const int b = tid & 63;
    const int q = tid >> 6;
    const int ping = t & 1;
    const float* __restrict__ hprev = g_hbuf[ping];
    float* __restrict__ hnew = g_hbuf[1 - ping];
    const float* __restrict__ Wz = (Kz == 256) ? Wr_in : g_Wrc;

    __shared__ float As[32][65];
    __shared__ float2 Ws[32][4];
    __shared__ float zs[64][8];

    const float* xwt = g_xw + (size_t)(t * 64 + b) * 1024;
    const int j0 = q * 256 + u0;
    float acc0 = xwt[j0];
    float acc1 = xwt[j0 + 1];

    for (int k0 = 0; k0 < Kz; k0 += 32) {
#pragma unroll
        for (int r = 0; r < 2; r++) {
            int idx = tid + r * 256;
            int ab = idx >> 3;
            int kf = (idx & 7) * 4;
            int kg = k0 + kf;
            const float* src = (kg < 256) ? (hprev + ab * 256 + kg)
                                          : (g_ctx + ab * 256 + (kg - 256));
            float4 v = *reinterpret_cast<const float4*>(src);
            As[kf + 0][ab] = v.x;
            As[kf + 1][ab] = v.y;
            As[kf + 2][ab] = v.z;
            As[kf + 3][ab] = v.w;
        }
        {
            int k = tid >> 3;
            int c = tid & 7;
            int j = (c >> 1) * 256 + u0 + (c & 1);
            ((float*)Ws)[k * 8 + c] = Wz[(size_t)(k0 + k) * 1024 + j];
        }
        __syncthreads();
#pragma unroll
        for (int k = 0; k < 32; k++) {
            float a = As[k][b];
            float2 w = Ws[k][q];
            acc0 += a * w.x;
            acc1 += a * w.y;
        }
        __syncthreads();
    }

    zs[b][q * 2 + 0] = acc0;
    zs[b][q * 2 + 1] = acc1;
    __syncthreads();

    if (tid < 128) {
        int du = tid >> 6;
        int bb = tid & 63;
        int u = u0 + du;
        float zi = zs[bb][0 + du];
        float zf = zs[bb][2 + du];
        float zg = zs[bb][4 + du];
        float zo = zs[bb][6 + du];
        float cold = g_c[bb * 256 + u];
        float cn = sigm(zf) * cold + sigm(zi) * tanhf(zg);
        g_c[bb * 256 + u] = cn;
        float h = sigm(zo) * tanhf(cn);
        hnew[bb * 256 + u] = h;
        g_hc[(size_t)(bb * T_ + t) * 512 + u] = h;
    }
}

// ---------------- per-step: attention ----------------
__global__ __launch_bounds__(256) void step_b_kernel(int t, const float* __restrict__ mem)
{
    const int b = blockIdx.x;
    const int tid = threadIdx.x;
    const int w = tid >> 5;
    const int l = tid & 31;
    const float* __restrict__ hcur = g_hbuf[1 - (t & 1)];

    __shared__ float hs[256];
    __shared__ float sc[32];
    __shared__ float al[32];

    hs[tid] = hcur[b * 256 + tid];
    __syncthreads();

    for (int s = w; s < S_; s += 8) {
        const float* kp = g_keys + (size_t)(b * S_ + s) * 256;
        float d = 0.0f;
#pragma unroll
        for (int i = 0; i < 8; i++) d += hs[l + 32 * i] * kp[l + 32 * i];
#pragma unroll
        for (int o = 16; o > 0; o >>= 1) d += __shfl_down_sync(0xffffffffu, d, o);
        if (l == 0) sc[s] = d;
    }
    __syncthreads();

    if (w == 0) {
        float v = (l < S_) ? sc[l] : -INFINITY;
        float mx = v;
#pragma unroll
        for (int o = 16; o > 0; o >>= 1) mx = fmaxf(mx, __shfl_xor_sync(0xffffffffu, mx, o));
        float e = (l < S_) ? expf(v - mx) : 0.0f;
        float sm = e;
#pragma unroll
        for (int o = 16; o > 0; o >>= 1) sm += __shfl_xor_sync(0xffffffffu, sm, o);
        if (l < S_) al[l] = e / sm;
    }
    __syncthreads();

    float c = 0.0f;
    const int u = tid;
#pragma unroll 1
    for (int s = 0; s < S_; s++)
        c += al[s] * mem[(size_t)(b * S_ + s) * 256 + u];
    g_ctx[b * 256 + u] = c;
    g_hc[(size_t)(b * T_ + t) * 512 + 256 + u] = c;
}

// ---------------- A' conversion: attn f32 -> bf16 split [hi | lo | hi] ----------------
__global__ void k_convA(const float* __restrict__ attn) {
    const int m = blockIdx.x;
    const int k = threadIdx.x;
    float v = attn[m * U_ + k];
    __nv_bfloat16 hi = __float2bfloat16(v);
    __nv_bfloat16 lo = __float2bfloat16(v - __bfloat162float(hi));
    size_t base = (size_t)m * FC_K + k;
    g_Abf[base] = hi;
    g_Abf[base + 256] = lo;
    g_Abf[base + 512] = hi;
}

// ---------------- W' conversion: W_fc [256][32000] -> Wt [32000][768] = [hi | hi | lo] ----------------
__global__ void k_convW(const float* __restrict__ W) {
    __shared__ float tile[32][33];
    const int n0 = blockIdx.x * 32;
    const int k0 = blockIdx.y * 32;
    const int tx = threadIdx.x;
    const int ty = threadIdx.y;   // 0..7
#pragma unroll
    for (int i = 0; i < 4; i++) {
        int k = ty + i * 8;
        tile[k][tx] = W[(size_t)(k0 + k) * V_ + n0 + tx];
    }
    __syncthreads();
#pragma unroll
    for (int i = 0; i < 4; i++) {
        int nr = ty + i * 8;
        float v = tile[tx][nr];
        __nv_bfloat16 hi = __float2bfloat16(v);
        __nv_bfloat16 lo = __float2bfloat16(v - __bfloat162float(hi));
        size_t base = (size_t)(n0 + nr) * FC_K + k0 + tx;
        g_Wt[base] = hi;
        g_Wt[base + 256] = hi;
        g_Wt[base + 512] = lo;
    }
}

// ---------------- HMMA FC GEMM: out[1920,32000] = A'(1920x768) @ Wt^T + b ----------------
// CTA 128x128, 8 warps of 64x32, BK=32, cp.async double buffer.
// SMEM tile rows: 64B data with 80B stride (bank-conflict-free ldmatrix).
#define TILE_B   10240                 // 128 rows * 80B
#define BUF_B    (2 * TILE_B)          // A+B per buffer
__global__ __launch_bounds__(256, 1)
void fc_hmma_kernel(const __nv_bfloat16* __restrict__ Abf,
                    const __nv_bfloat16* __restrict__ Wt,
                    const float* __restrict__ bias,
                    float* __restrict__ out)
{
    extern __shared__ char smem[];
    const uint32_t sbase = smem_u32(smem);
    const int tid = threadIdx.x;
    const int wid = tid >> 5;
    const int lane = tid & 31;
    const int n0 = blockIdx.x * 128;
    const int m0 = blockIdx.y * 128;

    const int warp_m = (wid >> 2) * 64;     // 0 or 64
    const int warp_nq = wid & 3;            // n quarter 0..3 -> n offset *32

    const char* Agl = (const char*)Abf + (size_t)m0 * (FC_K * 2);
    const char* Bgl = (const char*)Wt + (size_t)n0 * (FC_K * 2);

    float acc[4][4][4];
#pragma unroll
    for (int i = 0; i < 4; i++)
#pragma unroll
        for (int j = 0; j < 4; j++)
#pragma unroll
            for (int q = 0; q < 4; q++) acc[i][j][q] = 0.0f;

    // stage loader: 512 chunks A + 512 chunks B, 16B each; 256 threads x 2 each
#define LOADST(S, P)                                                            \
    do {                                                                        \
        const uint32_t dA = sbase + (P) * BUF_B;                                \
        const uint32_t dB = dA + TILE_B;                                        \
        _Pragma("unroll")                                                       \
        for (int i_ = 0; i_ < 2; i_++) {                                        \
            int id_ = tid + i_ * 256;                                           \
            int r_ = id_ >> 2, c_ = id_ & 3;                                    \
            cp16(dA + r_ * 80 + c_ * 16,                                        \
                 Agl + (size_t)r_ * (FC_K * 2) + (S) * 64 + c_ * 16);           \
            cp16(dB + r_ * 80 + c_ * 16,                                        \
                 Bgl + (size_t)r_ * (FC_K * 2) + (S) * 64 + c_ * 16);           \
        }                                                                       \
        asm volatile("cp.async.commit_group;" ::: "memory");                    \
    } while (0)

    LOADST(0, 0);
    LOADST(1, 1);

    // ldmatrix base offsets (per-lane), within a tile
    const uint32_t a_off = (uint32_t)((warp_m + (lane & 15)) * 80 + (lane >> 4) * 16);
    const uint32_t b_off = (uint32_t)((warp_nq * 32 + (lane >> 4) * 8 + (lane & 7)) * 80 +
                                      ((lane >> 3) & 1) * 16);

    for (int s = 0; s < FC_NS; s++) {
        if (s + 1 < FC_NS)
            asm volatile("cp.async.wait_group 1;" ::: "memory");
        else
            asm volatile("cp.async.wait_group 0;" ::: "memory");
        __syncthreads();

        const uint32_t sA = sbase + (s & 1) * BUF_B;
        const uint32_t sB = sA + TILE_B;
#pragma unroll
        for (int ks = 0; ks < 2; ks++) {
            uint32_t af[4][4];
#pragma unroll
            for (int mt = 0; mt < 4; mt++)
                ldm_x4(af[mt], sA + a_off + mt * (16 * 80) + ks * 32);
            uint32_t bf[2][4];
#pragma unroll
            for (int g = 0; g < 2; g++)
                ldm_x4(bf[g], sB + b_off + g * (16 * 80) + ks * 32);
#pragma unroll
            for (int mt = 0; mt < 4; mt++)
#pragma unroll
                for (int nt = 0; nt < 4; nt++)
                    mma16816(acc[mt][nt], af[mt],
                             bf[nt >> 1][(nt & 1) * 2], bf[nt >> 1][(nt & 1) * 2 + 1]);
        }
        __syncthreads();
        if (s + 2 < FC_NS) LOADST(s + 2, s & 1);
    }

    // ---- epilogue: regs -> SMEM (128x68 f32) -> coalesced STG + bias, 2 halves ----
    float* ep = (float*)smem;
    const int myhalf = warp_nq >> 1;
    const int colq = (warp_nq & 1) * 32;

#pragma unroll 1
    for (int h = 0; h < 2; h++) {
        __syncthreads();
        if (myhalf == h) {
#pragma unroll
            for (int mt = 0; mt < 4; mt++)
#pragma unroll
                for (int nt = 0; nt < 4; nt++) {
                    int row = warp_m + mt * 16 + (lane >> 2);
                    int col = colq + nt * 8 + (lane & 3) * 2;
                    ep[row * 68 + col]            = acc[mt][nt][0];
                    ep[row * 68 + col + 1]        = acc[mt][nt][1];
                    ep[(row + 8) * 68 + col]      = acc[mt][nt][2];
                    ep[(row + 8) * 68 + col + 1]  = acc[mt][nt][3];
                }
        }
        __syncthreads();
        const int gn0 = n0 + h * 64;
#pragma unroll
        for (int i = 0; i < 8; i++) {
            int idx = tid + i * 256;          // 2048 float4s
            int row = idx >> 4;
            int q = idx & 15;
            float4 v = *(const float4*)&ep[row * 68 + q * 4];
            float4 bb = *(const float4*)&bias[gn0 + q * 4];
            v.x += bb.x; v.y += bb.y; v.z += bb.z; v.w += bb.w;
            *(float4*)&out[(size_t)(m0 + row) * V_ + gn0 + q * 4] = v;
        }
    }
#undef LOADST
}

// ---------------- launcher ----------------
extern "C" void kernel_launch(void* const* d_in, const int* in_sizes, int n_in,
                              void* d_out, int out_size)
{
    const void*  inputs   = d_in[0];
    const float* memory   = (const float*)d_in[1];
    const float* sample_h = (const float*)d_in[2];
    const float* sample_c = (const float*)d_in[3];
    const float* emb      = (const float*)d_in[4];
    const float* W_k      = (const float*)d_in[5];
    const float* W_r      = (const float*)d_in[6];
    const float* b_lstm   = (const float*)d_in[7];
    const float* W_mem    = (const float*)d_in[8];
    const float* W_attn   = (const float*)d_in[9];
    const float* W_fc     = (const float*)d_in[10];
    const float* b_fc     = (const float*)d_in[11];
    float* out = (float*)d_out;

    float *p_keys, *p_xemb, *p_attn, *p_xw, *p_Wrc, *p_hc;
    __nv_bfloat16 *p_Abf, *p_Wt;
    cudaGetSymbolAddress((void**)&p_keys, g_keys);
    cudaGetSymbolAddress((void**)&p_xemb, g_xemb);
    cudaGetSymbolAddress((void**)&p_attn, g_attn);
    cudaGetSymbolAddress((void**)&p_Abf, g_Abf);
    cudaGetSymbolAddress((void**)&p_Wt, g_Wt);
    cudaGetSymbolAddress((void**)&p_xw, g_xw);
    cudaGetSymbolAddress((void**)&p_Wrc, g_Wrc);
    cudaGetSymbolAddress((void**)&p_hc, g_hc);

    // W' split+transpose (depends only on W_fc)
    k_convW<<<dim3(V_ / 32, U_ / 32), dim3(32, 8)>>>(W_fc);

    k_init<<<64, 256>>>(sample_h, sample_c);
    k_gather<<<B_ * T_, E_>>>(inputs, emb);
    sgemm_kernel<64, 64, 16, 4, 4><<<dim3(4, 31), 256>>>(memory, W_mem, nullptr, p_keys, 1984, 256, 256);
    sgemm_kernel<64, 64, 16, 4, 4><<<dim3(16, 30), 256>>>(p_xemb, W_k, b_lstm, p_xw, 1920, 1024, 128);
    sgemm_kernel<64, 64, 16, 4, 4><<<dim3(16, 8), 256>>>(W_attn, W_k + 128 * 1024, nullptr, p_Wrc, 512, 1024, 256);
    k_addWr<<<256, 1024>>>(W_r);

    for (int t = 0; t < T_; t++) {
        if (t == 0)
            step_a_kernel<<<128, 256>>>(t, W_r, 256);
        else
            step_a_kernel<<<128, 256>>>(t, W_r, 512);
        step_b_kernel<<<64, 256>>>(t, memory);
    }

    // attn_seq = hc_seq @ W_attn
    sgemm_kernel<64, 64, 16, 4, 4><<<dim3(4, 30), 256>>>(p_hc, W_attn, nullptr, p_attn, 1920, 256, 512);
    // A' split
    k_convA<<<B_ * T_, 256>>>(p_attn);

    // FC on tensor cores (HMMA mma.sync path — compiles on plain sm_103 target)
    cudaFuncSetAttribute(fc_hmma_kernel, cudaFuncAttributeMaxDynamicSharedMemorySize, BUF_B * 2);
    fc_hmma_kernel<<<dim3(V_ / 128, 15), 256, BUF_B * 2>>>(p_Abf, p_Wt, b_fc, out);
}

// round 6
// speedup vs baseline: 1.3853x; 1.1061x over previous
#include <cuda_runtime.h>
#include <cuda_bf16.h>
#include <math.h>
#include <stdint.h>

#define B_ 64
#define T_ 30
#define S_ 31
#define E_ 128
#define U_ 256
#define V_ 32000

#define FC_K   768
#define FC_NS  24          // K stages of 32

// ---------------- device scratch (no allocations allowed) ----------------
__device__ float g_keys[B_ * S_ * U_];
__device__ float g_xemb[B_ * T_ * E_];
__device__ float g_xw[B_ * T_ * 4 * U_];
__device__ float g_Wrc[2 * U_ * 4 * U_];
__device__ float g_hbuf[2][B_ * U_];
__device__ float g_c[B_ * U_];
__device__ float g_ctx[B_ * U_];
__device__ float g_hc[B_ * T_ * 2 * U_];
__device__ float g_attn[B_ * T_ * U_];
__device__ __nv_bfloat16 g_Abf[B_ * T_ * FC_K];       // [1920][768]  hi|lo|hi
__device__ __nv_bfloat16 g_Wt[(size_t)V_ * FC_K];     // [32000][768] hi|hi|lo

__device__ __forceinline__ float sigm(float x) { return 1.0f / (1.0f + expf(-x)); }
__device__ __forceinline__ uint32_t smem_u32(const void* p) {
    return (uint32_t)__cvta_generic_to_shared(p);
}
__device__ __forceinline__ void cp16(uint32_t dst, const void* src) {
    asm volatile("cp.async.cg.shared.global [%0], [%1], 16;" :: "r"(dst), "l"(src));
}
__device__ __forceinline__ void ldm_x4(uint32_t* r, uint32_t addr) {
    asm volatile("ldmatrix.sync.aligned.m8n8.x4.shared.b16 {%0,%1,%2,%3}, [%4];"
                 : "=r"(r[0]), "=r"(r[1]), "=r"(r[2]), "=r"(r[3]) : "r"(addr));
}
__device__ __forceinline__ void mma16816(float* c, const uint32_t* a, uint32_t b0, uint32_t b1) {
    asm volatile(
        "mma.sync.aligned.m16n8k16.row.col.f32.bf16.bf16.f32 "
        "{%0,%1,%2,%3}, {%4,%5,%6,%7}, {%8,%9}, {%0,%1,%2,%3};"
        : "+f"(c[0]), "+f"(c[1]), "+f"(c[2]), "+f"(c[3])
        : "r"(a[0]), "r"(a[1]), "r"(a[2]), "r"(a[3]), "r"(b0), "r"(b1));
}

// ---------------- init ----------------
__global__ void k_init(const float* __restrict__ h0, const float* __restrict__ c0) {
    int i = blockIdx.x * blockDim.x + threadIdx.x;
    if (i < B_ * U_) {
        g_hbuf[0][i] = h0[i];
        g_c[i] = c0[i];
        g_ctx[i] = 0.0f;
    }
}

// ---------------- gather embeddings (int32/int64 autodetect) ----------------
__global__ void k_gather(const void* __restrict__ in_raw, const float* __restrict__ emb) {
    const int m = blockIdx.x;
    const int t = m >> 6;
    const int b = m & 63;
    const int* p32 = (const int*)in_raw;
    bool is64 = true;
#pragma unroll
    for (int i = 1; i <= 15; i += 2)
        if (p32[i] != 0) is64 = false;
    const int pos = b * T_ + t;
    long long idx = is64 ? ((const long long*)in_raw)[pos] : (long long)p32[pos];
    g_xemb[m * E_ + threadIdx.x] = emb[idx * E_ + threadIdx.x];
}

// ---------------- generic fp32 tiled SGEMM (small GEMMs only) ----------------
template <int BM, int BN, int BK, int TM, int TN>
__global__ __launch_bounds__(256) void sgemm_kernel(
    const float* __restrict__ A, const float* __restrict__ B,
    const float* __restrict__ bias, float* __restrict__ C,
    int M, int N, int K)
{
    constexpr int TX = BN / TN;
    __shared__ float As[BK][BM];
    __shared__ float Bs[BK][BN];
    const int tid = threadIdx.x;
    const int tx = tid % TX;
    const int ty = tid / TX;
    const int row0 = blockIdx.y * BM;
    const int col0 = blockIdx.x * BN;

    const int a_m = tid / (BK / 4);
    const int a_k = (tid % (BK / 4)) * 4;
    const int b_k = tid / (BN / 4);
    const int b_n = (tid % (BN / 4)) * 4;

    float acc[TM][TN];
#pragma unroll
    for (int i = 0; i < TM; i++)
#pragma unroll
        for (int j = 0; j < TN; j++) acc[i][j] = 0.0f;

    for (int k0 = 0; k0 < K; k0 += BK) {
        float4 av = *reinterpret_cast<const float4*>(&A[(size_t)(row0 + a_m) * K + k0 + a_k]);
        As[a_k + 0][a_m] = av.x;
        As[a_k + 1][a_m] = av.y;
        As[a_k + 2][a_m] = av.z;
        As[a_k + 3][a_m] = av.w;
        *reinterpret_cast<float4*>(&Bs[b_k][b_n]) =
            *reinterpret_cast<const float4*>(&B[(size_t)(k0 + b_k) * N + col0 + b_n]);
        __syncthreads();
#pragma unroll
        for (int k = 0; k < BK; k++) {
            float ra[TM], rb[TN];
#pragma unroll
            for (int i = 0; i < TM; i++) ra[i] = As[k][ty * TM + i];
#pragma unroll
            for (int j = 0; j < TN; j++) rb[j] = Bs[k][tx * TN + j];
#pragma unroll
            for (int i = 0; i < TM; i++)
#pragma unroll
                for (int j = 0; j < TN; j++) acc[i][j] += ra[i] * rb[j];
        }
        __syncthreads();
    }

    float bj[TN];
#pragma unroll
    for (int j = 0; j < TN; j++)
        bj[j] = bias ? bias[col0 + tx * TN + j] : 0.0f;

#pragma unroll
    for (int i = 0; i < TM; i++) {
        const size_t row = row0 + ty * TM + i;
#pragma unroll
        for (int j = 0; j < TN; j += 4) {
            float4 v;
            v.x = acc[i][j + 0] + bj[j + 0];
            v.y = acc[i][j + 1] + bj[j + 1];
            v.z = acc[i][j + 2] + bj[j + 2];
            v.w = acc[i][j + 3] + bj[j + 3];
            *reinterpret_cast<float4*>(&C[row * N + col0 + tx * TN + j]) = v;
        }
    }
}

__global__ void k_addWr(const float* __restrict__ Wr) {
    int i = blockIdx.x * blockDim.x + threadIdx.x;
    if (i < U_ * 4 * U_) g_Wrc[i] += Wr[i];
}

// ---------------- per-step: z GEMM + LSTM ----------------
__global__ __launch_bounds__(256) void step_a_kernel(
    int t, const float* __restrict__ Wr_in, int Kz)
{
    const int u0 = blockIdx.x * 2;
    const int tid = threadIdx.x;
    const int b = tid & 63;
    const int q = tid >> 6;
    const int ping = t & 1;
    const float* __restrict__ hprev = g_hbuf[ping];
    float* __restrict__ hnew = g_hbuf[1 - ping];
    const float* __restrict__ Wz = (Kz == 256) ? Wr_in : g_Wrc;

    __shared__ float As[32][65];
    __shared__ float2 Ws[32][4];
    __shared__ float zs[64][8];

    const float* xwt = g_xw + (size_t)(t * 64 + b) * 1024;
    const int j0 = q * 256 + u0;
    float acc0 = xwt[j0];
    float acc1 = xwt[j0 + 1];

    for (int k0 = 0; k0 < Kz; k0 += 32) {
#pragma unroll
        for (int r = 0; r < 2; r++) {
            int idx = tid + r * 256;
            int ab = idx >> 3;
            int kf = (idx & 7) * 4;
            int kg = k0 + kf;
            const float* src = (kg < 256) ? (hprev + ab * 256 + kg)
                                          : (g_ctx + ab * 256 + (kg - 256));
            float4 v = *reinterpret_cast<const float4*>(src);
            As[kf + 0][ab] = v.x;
            As[kf + 1][ab] = v.y;
            As[kf + 2][ab] = v.z;
            As[kf + 3][ab] = v.w;
        }
        {
            int k = tid >> 3;
            int c = tid & 7;
            int j = (c >> 1) * 256 + u0 + (c & 1);
            ((float*)Ws)[k * 8 + c] = Wz[(size_t)(k0 + k) * 1024 + j];
        }
        __syncthreads();
#pragma unroll
        for (int k = 0; k < 32; k++) {
            float a = As[k][b];
            float2 w = Ws[k][q];
            acc0 += a * w.x;
            acc1 += a * w.y;
        }
        __syncthreads();
    }

    zs[b][q * 2 + 0] = acc0;
    zs[b][q * 2 + 1] = acc1;
    __syncthreads();

    if (tid < 128) {
        int du = tid >> 6;
        int bb = tid & 63;
        int u = u0 + du;
        float zi = zs[bb][0 + du];
        float zf = zs[bb][2 + du];
        float zg = zs[bb][4 + du];
        float zo = zs[bb][6 + du];
        float cold = g_c[bb * 256 + u];
        float cn = sigm(zf) * cold + sigm(zi) * tanhf(zg);
        g_c[bb * 256 + u] = cn;
        float h = sigm(zo) * tanhf(cn);
        hnew[bb * 256 + u] = h;
        g_hc[(size_t)(bb * T_ + t) * 512 + u] = h;
    }
}

// ---------------- per-step: attention ----------------
__global__ __launch_bounds__(256) void step_b_kernel(int t, const float* __restrict__ mem)
{
    const int b = blockIdx.x;
    const int tid = threadIdx.x;
    const int w = tid >> 5;
    const int l = tid & 31;
    const float* __restrict__ hcur = g_hbuf[1 - (t & 1)];

    __shared__ float hs[256];
    __shared__ float sc[32];
    __shared__ float al[32];

    hs[tid] = hcur[b * 256 + tid];
    __syncthreads();

    for (int s = w; s < S_; s += 8) {
        const float* kp = g_keys + (size_t)(b * S_ + s) * 256;
        float d = 0.0f;
#pragma unroll
        for (int i = 0; i < 8; i++) d += hs[l + 32 * i] * kp[l + 32 * i];
#pragma unroll
        for (int o = 16; o > 0; o >>= 1) d += __shfl_down_sync(0xffffffffu, d, o);
        if (l == 0) sc[s] = d;
    }
    __syncthreads();

    if (w == 0) {
        float v = (l < S_) ? sc[l] : -INFINITY;
        float mx = v;
#pragma unroll
        for (int o = 16; o > 0; o >>= 1) mx = fmaxf(mx, __shfl_xor_sync(0xffffffffu, mx, o));
        float e = (l < S_) ? expf(v - mx) : 0.0f;
        float sm = e;
#pragma unroll
        for (int o = 16; o > 0; o >>= 1) sm += __shfl_xor_sync(0xffffffffu, sm, o);
        if (l < S_) al[l] = e / sm;
    }
    __syncthreads();

    float c = 0.0f;
    const int u = tid;
#pragma unroll 1
    for (int s = 0; s < S_; s++)
        c += al[s] * mem[(size_t)(b * S_ + s) * 256 + u];
    g_ctx[b * 256 + u] = c;
    g_hc[(size_t)(b * T_ + t) * 512 + 256 + u] = c;
}

// ---------------- A' conversion: attn f32 -> bf16 split [hi | lo | hi] ----------------
__global__ void k_convA(const float* __restrict__ attn) {
    const int m = blockIdx.x;
    const int k = threadIdx.x;
    float v = attn[m * U_ + k];
    __nv_bfloat16 hi = __float2bfloat16(v);
    __nv_bfloat16 lo = __float2bfloat16(v - __bfloat162float(hi));
    size_t base = (size_t)m * FC_K + k;
    g_Abf[base] = hi;
    g_Abf[base + 256] = lo;
    g_Abf[base + 512] = hi;
}

// ---------------- W' conversion: W_fc [256][32000] -> Wt [32000][768] = [hi | hi | lo] ----------------
__global__ void k_convW(const float* __restrict__ W) {
    __shared__ float tile[32][33];
    const int n0 = blockIdx.x * 32;
    const int k0 = blockIdx.y * 32;
    const int tx = threadIdx.x;
    const int ty = threadIdx.y;   // 0..7
#pragma unroll
    for (int i = 0; i < 4; i++) {
        int k = ty + i * 8;
        tile[k][tx] = W[(size_t)(k0 + k) * V_ + n0 + tx];
    }
    __syncthreads();
#pragma unroll
    for (int i = 0; i < 4; i++) {
        int nr = ty + i * 8;
        float v = tile[tx][nr];
        __nv_bfloat16 hi = __float2bfloat16(v);
        __nv_bfloat16 lo = __float2bfloat16(v - __bfloat162float(hi));
        size_t base = (size_t)(n0 + nr) * FC_K + k0 + tx;
        g_Wt[base] = hi;
        g_Wt[base + 256] = hi;
        g_Wt[base + 512] = lo;
    }
}

// ---------------- HMMA FC GEMM: out[1920,32000] = A'(1920x768) @ Wt^T + b ----------------
// CTA 128x128, 8 warps of 64x32, BK=32, cp.async TRIPLE buffer, one sync/stage,
// 2 CTAs/SM co-residency.
#define TILE_B   10240                 // 128 rows * 80B
#define BUF_B    (2 * TILE_B)          // A+B per buffer (20 KB)
__global__ __launch_bounds__(256, 2)
void fc_hmma_kernel(const __nv_bfloat16* __restrict__ Abf,
                    const __nv_bfloat16* __restrict__ Wt,
                    const float* __restrict__ bias,
                    float* __restrict__ out)
{
    extern __shared__ char smem[];
    const uint32_t sbase = smem_u32(smem);
    const int tid = threadIdx.x;
    const int wid = tid >> 5;
    const int lane = tid & 31;
    const int n0 = blockIdx.x * 128;
    const int m0 = blockIdx.y * 128;

    const int warp_m = (wid >> 2) * 64;     // 0 or 64
    const int warp_nq = wid & 3;            // n quarter 0..3 -> n offset *32

    const char* Agl = (const char*)Abf + (size_t)m0 * (FC_K * 2);
    const char* Bgl = (const char*)Wt + (size_t)n0 * (FC_K * 2);

    float acc[4][4][4];
#pragma unroll
    for (int i = 0; i < 4; i++)
#pragma unroll
        for (int j = 0; j < 4; j++)
#pragma unroll
            for (int q = 0; q < 4; q++) acc[i][j][q] = 0.0f;

    // stage loader: 512 chunks A + 512 chunks B, 16B each; 256 threads x 4 cp16
#define LOADST(S, P)                                                            \
    do {                                                                        \
        const uint32_t dA = sbase + (P) * BUF_B;                                \
        const uint32_t dB = dA + TILE_B;                                        \
        _Pragma("unroll")                                                       \
        for (int i_ = 0; i_ < 2; i_++) {                                        \
            int id_ = tid + i_ * 256;                                           \
            int r_ = id_ >> 2, c_ = id_ & 3;                                    \
            cp16(dA + r_ * 80 + c_ * 16,                                        \
                 Agl + (size_t)r_ * (FC_K * 2) + (S) * 64 + c_ * 16);           \
            cp16(dB + r_ * 80 + c_ * 16,                                        \
                 Bgl + (size_t)r_ * (FC_K * 2) + (S) * 64 + c_ * 16);           \
        }                                                                       \
        asm volatile("cp.async.commit_group;" ::: "memory");                    \
    } while (0)

    LOADST(0, 0);
    LOADST(1, 1);

    // ldmatrix base offsets (per-lane), within a tile
    const uint32_t a_off = (uint32_t)((warp_m + (lane & 15)) * 80 + (lane >> 4) * 16);
    const uint32_t b_off = (uint32_t)((warp_nq * 32 + (lane >> 4) * 8 + (lane & 7)) * 80 +
                                      ((lane >> 3) & 1) * 16);

    for (int s = 0; s < FC_NS; s++) {
        if (s < FC_NS - 1)
            asm volatile("cp.async.wait_group 1;" ::: "memory");
        else
            asm volatile("cp.async.wait_group 0;" ::: "memory");
        __syncthreads();

        // prefetch stage s+2 into buffer (s+2)%3 (held stage s-1, already consumed)
        if (s + 2 < FC_NS) {
            const int pb = (s + 2) % 3;
            LOADST(s + 2, pb);
        }

        const uint32_t sA = sbase + (uint32_t)(s % 3) * BUF_B;
        const uint32_t sB = sA + TILE_B;
#pragma unroll
        for (int ks = 0; ks < 2; ks++) {
            uint32_t af[4][4];
#pragma unroll
            for (int mt = 0; mt < 4; mt++)
                ldm_x4(af[mt], sA + a_off + mt * (16 * 80) + ks * 32);
            uint32_t bf[2][4];
#pragma unroll
            for (int g = 0; g < 2; g++)
                ldm_x4(bf[g], sB + b_off + g * (16 * 80) + ks * 32);
#pragma unroll
            for (int mt = 0; mt < 4; mt++)
#pragma unroll
                for (int nt = 0; nt < 4; nt++)
                    mma16816(acc[mt][nt], af[mt],
                             bf[nt >> 1][(nt & 1) * 2], bf[nt >> 1][(nt & 1) * 2 + 1]);
        }
    }

    // ---- epilogue: regs -> SMEM (128x68 f32) -> coalesced STG + bias, 2 halves ----
    float* ep = (float*)smem;
    const int myhalf = warp_nq >> 1;
    const int colq = (warp_nq & 1) * 32;

#pragma unroll 1
    for (int h = 0; h < 2; h++) {
        __syncthreads();
        if (myhalf == h) {
#pragma unroll
            for (int mt = 0; mt < 4; mt++)
#pragma unroll
                for (int nt = 0; nt < 4; nt++) {
                    int row = warp_m + mt * 16 + (lane >> 2);
                    int col = colq + nt * 8 + (lane & 3) * 2;
                    ep[row * 68 + col]            = acc[mt][nt][0];
                    ep[row * 68 + col + 1]        = acc[mt][nt][1];
                    ep[(row + 8) * 68 + col]      = acc[mt][nt][2];
                    ep[(row + 8) * 68 + col + 1]  = acc[mt][nt][3];
                }
        }
        __syncthreads();
        const int gn0 = n0 + h * 64;
#pragma unroll
        for (int i = 0; i < 8; i++) {
            int idx = tid + i * 256;          // 2048 float4s
            int row = idx >> 4;
            int q = idx & 15;
            float4 v = *(const float4*)&ep[row * 68 + q * 4];
            float4 bb = *(const float4*)&bias[gn0 + q * 4];
            v.x += bb.x; v.y += bb.y; v.z += bb.z; v.w += bb.w;
            *(float4*)&out[(size_t)(m0 + row) * V_ + gn0 + q * 4] = v;
        }
    }
#undef LOADST
}

// ---------------- launcher ----------------
extern "C" void kernel_launch(void* const* d_in, const int* in_sizes, int n_in,
                              void* d_out, int out_size)
{
    const void*  inputs   = d_in[0];
    const float* memory   = (const float*)d_in[1];
    const float* sample_h = (const float*)d_in[2];
    const float* sample_c = (const float*)d_in[3];
    const float* emb      = (const float*)d_in[4];
    const float* W_k      = (const float*)d_in[5];
    const float* W_r      = (const float*)d_in[6];
    const float* b_lstm   = (const float*)d_in[7];
    const float* W_mem    = (const float*)d_in[8];
    const float* W_attn   = (const float*)d_in[9];
    const float* W_fc     = (const float*)d_in[10];
    const float* b_fc     = (const float*)d_in[11];
    float* out = (float*)d_out;

    float *p_keys, *p_xemb, *p_attn, *p_xw, *p_Wrc, *p_hc;
    __nv_bfloat16 *p_Abf, *p_Wt;
    cudaGetSymbolAddress((void**)&p_keys, g_keys);
    cudaGetSymbolAddress((void**)&p_xemb, g_xemb);
    cudaGetSymbolAddress((void**)&p_attn, g_attn);
    cudaGetSymbolAddress((void**)&p_Abf, g_Abf);
    cudaGetSymbolAddress((void**)&p_Wt, g_Wt);
    cudaGetSymbolAddress((void**)&p_xw, g_xw);
    cudaGetSymbolAddress((void**)&p_Wrc, g_Wrc);
    cudaGetSymbolAddress((void**)&p_hc, g_hc);

    // W' split+transpose (depends only on W_fc)
    k_convW<<<dim3(V_ / 32, U_ / 32), dim3(32, 8)>>>(W_fc);

    k_init<<<64, 256>>>(sample_h, sample_c);
    k_gather<<<B_ * T_, E_>>>(inputs, emb);
    sgemm_kernel<64, 64, 16, 4, 4><<<dim3(4, 31), 256>>>(memory, W_mem, nullptr, p_keys, 1984, 256, 256);
    sgemm_kernel<64, 64, 16, 4, 4><<<dim3(16, 30), 256>>>(p_xemb, W_k, b_lstm, p_xw, 1920, 1024, 128);
    sgemm_kernel<64, 64, 16, 4, 4><<<dim3(16, 8), 256>>>(W_attn, W_k + 128 * 1024, nullptr, p_Wrc, 512, 1024, 256);
    k_addWr<<<256, 1024>>>(W_r);

    for (int t = 0; t < T_; t++) {
        if (t == 0)
            step_a_kernel<<<128, 256>>>(t, W_r, 256);
        else
            step_a_kernel<<<128, 256>>>(t, W_r, 512);
        step_b_kernel<<<64, 256>>>(t, memory);
    }

    // attn_seq = hc_seq @ W_attn
    sgemm_kernel<64, 64, 16, 4, 4><<<dim3(4, 30), 256>>>(p_hc, W_attn, nullptr, p_attn, 1920, 256, 512);
    // A' split
    k_convA<<<B_ * T_, 256>>>(p_attn);

    // FC on tensor cores (HMMA mma.sync path), triple-buffered, 2 CTA/SM
    cudaFuncSetAttribute(fc_hmma_kernel, cudaFuncAttributeMaxDynamicSharedMemorySize, 3 * BUF_B);
    fc_hmma_kernel<<<dim3(V_ / 128, 15), 256, 3 * BUF_B>>>(p_Abf, p_Wt, b_fc, out);
}